// round 6
// baseline (speedup 1.0000x reference)
#include <cuda_runtime.h>
#include <float.h>
#include <math.h>

// ---------------------------------------------------------------------------
// Problem constants (from reference)
// ---------------------------------------------------------------------------
#define BB    8
#define NN    2048
#define KNNK  20
#define CIN   67          // 3 xyz + 64 feat
#define CFE   64          // feature channels
#define CCC   144         // concat channels: 64 gpn + 64 center + 16 pos
#define CH    64          // hidden
#define DIMV  16
#define DIMK  32
#define NHEAD 8
#define COUT  128
#define EPSF  1e-5f
#define XYZ_TOT (BB*NN*3)

// scratch: neighbor indices (allowed: __device__ global, no allocation)
__device__ int g_idx[BB * NN * KNNK];

// ---------------------------------------------------------------------------
// Kernel 1: brute-force KNN (top-20 smallest squared distance, incl. self)
// one block = 8 queries of one batch, one warp per query.
// ---------------------------------------------------------------------------
__global__ void knn_kernel(const float* __restrict__ x)
{
    extern __shared__ float sm[];
    float* sx   = sm;            // [NN]
    float* sy   = sx + NN;       // [NN]
    float* sz   = sy + NN;       // [NN]
    float* ss   = sz + NN;       // [NN]  squared norms
    float* dist = ss + NN;       // [8][NN]

    const int b     = blockIdx.x >> 8;          // 256 blocks per batch
    const int qbase = (blockIdx.x & 255) << 3;  // 8 queries per block
    const int t     = threadIdx.x;
    const int w     = t >> 5;
    const int lane  = t & 31;

    // stage batch xyz + norms
    for (int j = t; j < NN; j += 256) {
        const float* p = x + ((size_t)b * NN + j) * CIN;
        float a0 = p[0], a1 = p[1], a2 = p[2];
        sx[j] = a0; sy[j] = a1; sz[j] = a2;
        ss[j] = a0 * a0 + a1 * a1 + a2 * a2;
    }
    __syncthreads();

    const int n = qbase + w;
    const float qx = sx[n], qy = sy[n], qz = sz[n], sq = ss[n];
    float* dw = dist + w * NN;

    for (int j = lane; j < NN; j += 32) {
        float dot = qx * sx[j] + qy * sy[j] + qz * sz[j];
        dw[j] = -2.0f * dot + sq + ss[j];     // matches ref formula/order
    }
    __syncwarp();

    // 20 iterative warp arg-min passes (tie -> lowest index, like top_k)
    for (int sel = 0; sel < KNNK; sel++) {
        float bv = FLT_MAX;
        int   bi = 0x7fffffff;
        for (int j = lane; j < NN; j += 32) {
            float v = dw[j];
            if (v < bv) { bv = v; bi = j; }   // strict <: keeps lowest index on tie
        }
        #pragma unroll
        for (int o = 16; o; o >>= 1) {
            float ov = __shfl_xor_sync(0xffffffffu, bv, o);
            int   oi = __shfl_xor_sync(0xffffffffu, bi, o);
            if (ov < bv || (ov == bv && oi < bi)) { bv = ov; bi = oi; }
        }
        if (lane == 0) {
            g_idx[((size_t)b * NN + n) * KNNK + sel] = bi;
            dw[bi] = FLT_MAX;
        }
        __syncwarp();
    }
}

// ---------------------------------------------------------------------------
// helpers
// ---------------------------------------------------------------------------
__device__ __forceinline__ float dot4(float4 a, float4 b)
{
    return a.x * b.x + a.y * b.y + a.z * b.z + a.w * b.w;
}

// full-block (128 thread) sum reduce with broadcast
__device__ __forceinline__ float block_sum_128(float v, float* sred, float* sbc)
{
    #pragma unroll
    for (int o = 16; o; o >>= 1) v += __shfl_xor_sync(0xffffffffu, v, o);
    if ((threadIdx.x & 31) == 0) sred[threadIdx.x >> 5] = v;
    __syncthreads();
    if (threadIdx.x == 0) *sbc = sred[0] + sred[1] + sred[2] + sred[3];
    __syncthreads();
    return *sbc;
}

// ---------------------------------------------------------------------------
// Kernel 2: fused per-point transformer block. One block per (b, n).
// ---------------------------------------------------------------------------
__global__ void __launch_bounds__(128)
fused_kernel(const float* __restrict__ x,
             const float* __restrict__ Wh,
             const float* __restrict__ W1, const float* __restrict__ g1, const float* __restrict__ b1,
             const float* __restrict__ W2, const float* __restrict__ g2, const float* __restrict__ b2,
             const float* __restrict__ Wq, const float* __restrict__ lnqw, const float* __restrict__ lnqb,
             const float* __restrict__ Wv, const float* __restrict__ lnvw, const float* __restrict__ lnvb,
             const float* __restrict__ Wk,
             const float* __restrict__ lnow, const float* __restrict__ lnob,
             float* __restrict__ out)
{
    const int bn = blockIdx.x;
    const int b  = bn >> 11;            // / 2048
    const int n  = bn & (NN - 1);
    const int t  = threadIdx.x;

    __shared__ __align__(16) float sF [KNNK * CCC];     // 20 x 144
    __shared__ __align__(16) float sH1[KNNK * CH];      // 20 x 64
    __shared__ __align__(16) float sH2[KNNK * CH];      // 20 x 64
    __shared__ __align__(16) float sFQ[CH];             // 64
    __shared__ __align__(16) float sQ [NHEAD * DIMK];   // 256
    __shared__ __align__(16) float sV [KNNK * DIMV];    // 20 x 16
    __shared__ __align__(16) float sKK[KNNK * DIMK];    // 20 x 32
    __shared__ __align__(16) float sKV[DIMK * DIMV];    // 32 x 16
    __shared__ __align__(16) float sCF[CFE];
    __shared__ int   sIdx[KNNK];
    __shared__ float sred[4];
    __shared__ float sbc[1];

    const float* xb = x + (size_t)b * NN * CIN;
    const float* xc = xb + (size_t)n * CIN;
    const float cx = xc[0], cy = xc[1], cz = xc[2];

    if (t < CFE)  sCF[t]  = xc[3 + t];
    if (t < KNNK) sIdx[t] = g_idx[(size_t)bn * KNNK + t];
    __syncthreads();

    // ---- build F = [grouped - center | center | pos] -----------------------
    for (int i = t; i < KNNK * CFE; i += 128) {
        const int k = i >> 6, c = i & 63;
        const float* np = xb + (size_t)sIdx[k] * CIN;
        const float cf = sCF[c];
        sF[k * CCC + c]        = np[3 + c] - cf;
        sF[k * CCC + CFE + c]  = cf;
    }
    for (int i = t; i < KNNK * DIMV; i += 128) {
        const int k = i / DIMV, vd = i % DIMV;
        const float* np = xb + (size_t)sIdx[k] * CIN;
        const float rx = np[0] - cx, ry = np[1] - cy, rz = np[2] - cz;
        sF[k * CCC + 2 * CFE + vd] =
            Wh[vd * 3 + 0] * rx + Wh[vd * 3 + 1] * ry + Wh[vd * 3 + 2] * rz;
    }
    __syncthreads();

    const float bn_rs = rsqrtf(1.0f + EPSF);

    // ---- GEMM1: h1 = relu(bn1(W1 @ F)),  thread = (o, k-group of 10) -------
    {
        const int o  = t & 63;
        const int kg = t >> 6;             // 0 or 1; k = kg + 2*j
        float acc[10];
        #pragma unroll
        for (int j = 0; j < 10; j++) acc[j] = 0.f;
        const float4* w4 = (const float4*)(W1 + o * CCC);
        #pragma unroll 4
        for (int c4 = 0; c4 < CCC / 4; c4++) {
            const float4 w = w4[c4];
            #pragma unroll
            for (int j = 0; j < 10; j++) {
                const float4 f = *(const float4*)&sF[(kg + 2 * j) * CCC + 4 * c4];
                acc[j] += dot4(w, f);
            }
        }
        const float sc = g1[o] * bn_rs;
        const float bo = b1[o];
        #pragma unroll
        for (int j = 0; j < 10; j++)
            sH1[(kg + 2 * j) * CH + o] = fmaxf(acc[j] * sc + bo, 0.f);
    }
    __syncthreads();

    // ---- GEMM2: h2 = relu(bn2(W2 @ h1)) -------------------------------------
    {
        const int o  = t & 63;
        const int kg = t >> 6;
        float acc[10];
        #pragma unroll
        for (int j = 0; j < 10; j++) acc[j] = 0.f;
        const float4* w4 = (const float4*)(W2 + o * CH);
        #pragma unroll 4
        for (int c4 = 0; c4 < CH / 4; c4++) {
            const float4 w = w4[c4];
            #pragma unroll
            for (int j = 0; j < 10; j++) {
                const float4 f = *(const float4*)&sH1[(kg + 2 * j) * CH + 4 * c4];
                acc[j] += dot4(w, f);
            }
        }
        const float sc = g2[o] * bn_rs;
        const float bo = b2[o];
        #pragma unroll
        for (int j = 0; j < 10; j++)
            sH2[(kg + 2 * j) * CH + o] = fmaxf(acc[j] * sc + bo, 0.f);
    }
    __syncthreads();

    // ---- feature_q = max over k ---------------------------------------------
    if (t < CH) {
        float m = sH2[t];
        #pragma unroll
        for (int k = 1; k < KNNK; k++) m = fmaxf(m, sH2[k * CH + t]);
        sFQ[t] = m;
    }
    __syncthreads();

    // ---- q = relu(LN(W_q @ fq)) over 256 ------------------------------------
    {
        float qv[2];
        #pragma unroll
        for (int r = 0; r < 2; r++) {
            const int o = t + r * 128;
            const float4* w4 = (const float4*)(Wq + o * CH);
            float acc = 0.f;
            #pragma unroll
            for (int c4 = 0; c4 < CH / 4; c4++)
                acc += dot4(w4[c4], *(const float4*)&sFQ[4 * c4]);
            qv[r] = acc;
        }
        const float s    = block_sum_128(qv[0] + qv[1], sred, sbc);
        const float mean = s * (1.f / 256.f);
        const float d0 = qv[0] - mean, d1 = qv[1] - mean;
        const float vs   = block_sum_128(d0 * d0 + d1 * d1, sred, sbc);
        const float inv  = rsqrtf(vs * (1.f / 256.f) + EPSF);
        #pragma unroll
        for (int r = 0; r < 2; r++) {
            const int o = t + r * 128;
            sQ[o] = fmaxf((qv[r] - mean) * inv * lnqw[o] + lnqb[o], 0.f);
        }
    }

    // ---- v = LN_16(W_v @ F) ---------------------------------------------------
    for (int i = t; i < KNNK * DIMV; i += 128) {
        const int k = i >> 4, vd = i & 15;
        const float4* w4 = (const float4*)(Wv + vd * CCC);
        float acc = 0.f;
        #pragma unroll
        for (int c4 = 0; c4 < CCC / 4; c4++)
            acc += dot4(w4[c4], *(const float4*)&sF[k * CCC + 4 * c4]);
        sV[i] = acc;
    }
    __syncthreads();
    if (t < KNNK) {
        float m = 0.f;
        #pragma unroll
        for (int vd = 0; vd < DIMV; vd++) m += sV[t * DIMV + vd];
        m *= (1.f / DIMV);
        float var = 0.f;
        #pragma unroll
        for (int vd = 0; vd < DIMV; vd++) {
            const float d = sV[t * DIMV + vd] - m;
            var += d * d;
        }
        var *= (1.f / DIMV);
        const float inv = rsqrtf(var + EPSF);
        #pragma unroll
        for (int vd = 0; vd < DIMV; vd++)
            sV[t * DIMV + vd] = (sV[t * DIMV + vd] - m) * inv * lnvw[vd] + lnvb[vd];
    }

    // ---- kk = softmax_k(W_k @ F) ---------------------------------------------
    for (int i = t; i < KNNK * DIMK; i += 128) {
        const int k = i >> 5, d = i & 31;
        const float4* w4 = (const float4*)(Wk + d * CCC);
        float acc = 0.f;
        #pragma unroll
        for (int c4 = 0; c4 < CCC / 4; c4++)
            acc += dot4(w4[c4], *(const float4*)&sF[k * CCC + 4 * c4]);
        sKK[i] = acc;
    }
    __syncthreads();
    if (t < DIMK) {
        float mx = -FLT_MAX;
        #pragma unroll
        for (int k = 0; k < KNNK; k++) mx = fmaxf(mx, sKK[k * DIMK + t]);
        float sum = 0.f;
        #pragma unroll
        for (int k = 0; k < KNNK; k++) {
            const float e = expf(sKK[k * DIMK + t] - mx);
            sKK[k * DIMK + t] = e;
            sum += e;
        }
        const float inv = 1.f / sum;
        #pragma unroll
        for (int k = 0; k < KNNK; k++) sKK[k * DIMK + t] *= inv;
    }
    __syncthreads();

    // ---- kv[d][v] = sum_k kk[k][d] * v[k][v] -----------------------------------
    for (int i = t; i < DIMK * DIMV; i += 128) {
        const int d = i >> 4, vd = i & 15;
        float acc = 0.f;
        #pragma unroll
        for (int k = 0; k < KNNK; k++)
            acc += sKK[k * DIMK + d] * sV[k * DIMV + vd];
        sKV[i] = acc;
    }
    __syncthreads();

    // ---- out = LN_128(q @ kv), write transposed ---------------------------------
    {
        const int h = t >> 4, vd = t & 15;
        float acc = 0.f;
        #pragma unroll
        for (int d = 0; d < DIMK; d++)
            acc += sQ[h * DIMK + d] * sKV[d * DIMV + vd];

        const float s    = block_sum_128(acc, sred, sbc);
        const float mean = s * (1.f / COUT);
        const float dd   = acc - mean;
        const float vs   = block_sum_128(dd * dd, sred, sbc);
        const float inv  = rsqrtf(vs * (1.f / COUT) + EPSF);
        const float ov   = (acc - mean) * inv * lnow[t] + lnob[t];

        // out layout: [xyz (B,N,3)] then [outT (B,128,N)]
        out[XYZ_TOT + ((size_t)b * COUT + t) * NN + n] = ov;
    }
    if (t < 3) {
        const float v = (t == 0) ? cx : ((t == 1) ? cy : cz);
        out[(size_t)bn * 3 + t] = v;
    }
}

// ---------------------------------------------------------------------------
// launch
// ---------------------------------------------------------------------------
extern "C" void kernel_launch(void* const* d_in, const int* in_sizes, int n_in,
                              void* d_out, int out_size)
{
    const float* x    = (const float*)d_in[0];
    const float* Wh   = (const float*)d_in[1];
    const float* W1   = (const float*)d_in[2];
    const float* g1   = (const float*)d_in[3];
    const float* b1   = (const float*)d_in[4];
    const float* W2   = (const float*)d_in[5];
    const float* g2   = (const float*)d_in[6];
    const float* b2   = (const float*)d_in[7];
    const float* Wq   = (const float*)d_in[8];
    const float* lnqw = (const float*)d_in[9];
    const float* lnqb = (const float*)d_in[10];
    const float* Wv   = (const float*)d_in[11];
    const float* lnvw = (const float*)d_in[12];
    const float* lnvb = (const float*)d_in[13];
    const float* Wk   = (const float*)d_in[14];
    const float* lnow = (const float*)d_in[15];
    const float* lnob = (const float*)d_in[16];
    float* out = (float*)d_out;

    const int knn_smem = (4 * NN + 8 * NN) * (int)sizeof(float);  // 96 KB
    cudaFuncSetAttribute(knn_kernel,
                         cudaFuncAttributeMaxDynamicSharedMemorySize, knn_smem);

    knn_kernel<<<BB * (NN / 8), 256, knn_smem>>>(x);

    fused_kernel<<<BB * NN, 128>>>(x, Wh,
                                   W1, g1, b1,
                                   W2, g2, b2,
                                   Wq, lnqw, lnqb,
                                   Wv, lnvw, lnvb,
                                   Wk, lnow, lnob,
                                   out);
}

// round 7
// speedup vs baseline: 1.9809x; 1.9809x over previous
#include <cuda_runtime.h>
#include <float.h>
#include <math.h>

// ---------------------------------------------------------------------------
// Problem constants
// ---------------------------------------------------------------------------
#define BB    8
#define NN    2048
#define KNNK  20
#define CIN   67          // 3 xyz + 64 feat
#define CFE   64
#define CCC   144         // 64 gpn + 64 center + 16 pos
#define CH    64
#define DIMV  16
#define DIMK  32
#define NHEAD 8
#define COUT  128
#define EPSF  1e-5f
#define XYZ_TOT (BB*NN*3)

typedef unsigned long long ull;

// scratch (no allocation allowed -> __device__ globals)
__device__ int    g_idx[BB * NN * KNNK];
__device__ float4 W1p[(CCC/4) * CH];            // [c4][o]   36*64
__device__ float4 W2p[(CH/4)  * CH];            // [c4][o]   16*64
__device__ float4 Wqp[(CH/4)  * (NHEAD*DIMK)];  // [c4][o]   16*256
__device__ float4 Wvp[(CCC/4) * DIMV];          // [c4][vd]  36*16
__device__ float4 Wkp[(CCC/4) * DIMK];          // [c4][d]   36*32

// ---------------------------------------------------------------------------
// packed dual-fp32 FMA helpers (Blackwell f32x2 pipe)
// ---------------------------------------------------------------------------
__device__ __forceinline__ void ffma2(ull& d, ull a, ull b)
{
    asm("fma.rn.f32x2 %0, %1, %2, %0;" : "+l"(d) : "l"(a), "l"(b));
}
__device__ __forceinline__ float hsum2(ull v)
{
    float lo, hi;
    asm("mov.b64 {%0, %1}, %2;" : "=f"(lo), "=f"(hi) : "l"(v));
    return lo + hi;
}
__device__ __forceinline__ ulonglong2 ldp(const void* p)
{
    return *(const ulonglong2*)p;
}

// ---------------------------------------------------------------------------
// Kernel 0: pack weights into coalesced transposed layouts
// ---------------------------------------------------------------------------
__global__ void pack_weights(const float* __restrict__ W1, const float* __restrict__ W2,
                             const float* __restrict__ Wq, const float* __restrict__ Wv,
                             const float* __restrict__ Wk)
{
    int i = blockIdx.x * blockDim.x + threadIdx.x;
    if (i < (CCC/4)*CH) {
        int c4 = i >> 6, o = i & 63;
        W1p[i] = *(const float4*)&W1[o * CCC + 4 * c4];
        return;
    }
    i -= (CCC/4)*CH;
    if (i < (CH/4)*CH) {
        int c4 = i >> 6, o = i & 63;
        W2p[i] = *(const float4*)&W2[o * CH + 4 * c4];
        return;
    }
    i -= (CH/4)*CH;
    if (i < (CH/4)*NHEAD*DIMK) {
        int c4 = i >> 8, o = i & 255;
        Wqp[i] = *(const float4*)&Wq[o * CH + 4 * c4];
        return;
    }
    i -= (CH/4)*NHEAD*DIMK;
    if (i < (CCC/4)*DIMV) {
        int c4 = i >> 4, vd = i & 15;
        Wvp[i] = *(const float4*)&Wv[vd * CCC + 4 * c4];
        return;
    }
    i -= (CCC/4)*DIMV;
    if (i < (CCC/4)*DIMK) {
        int c4 = i >> 5, d = i & 31;
        Wkp[i] = *(const float4*)&Wk[d * CCC + 4 * c4];
    }
}

// ---------------------------------------------------------------------------
// Kernel 1: brute-force KNN (top-20 smallest sqdist). 1 warp per query.
// ---------------------------------------------------------------------------
__global__ void knn_kernel(const float* __restrict__ x)
{
    extern __shared__ float sm[];
    float* sx   = sm;
    float* sy   = sx + NN;
    float* sz   = sy + NN;
    float* ss   = sz + NN;
    float* dist = ss + NN;      // [8][NN]

    const int b     = blockIdx.x >> 8;
    const int qbase = (blockIdx.x & 255) << 3;
    const int t     = threadIdx.x;
    const int w     = t >> 5;
    const int lane  = t & 31;

    for (int j = t; j < NN; j += 256) {
        const float* p = x + ((size_t)b * NN + j) * CIN;
        float a0 = p[0], a1 = p[1], a2 = p[2];
        sx[j] = a0; sy[j] = a1; sz[j] = a2;
        ss[j] = a0 * a0 + a1 * a1 + a2 * a2;
    }
    __syncthreads();

    const int n = qbase + w;
    const float qx = sx[n], qy = sy[n], qz = sz[n], sq = ss[n];
    float* dw = dist + w * NN;

    for (int j = lane; j < NN; j += 32) {
        float dot = qx * sx[j] + qy * sy[j] + qz * sz[j];
        dw[j] = -2.0f * dot + sq + ss[j];
    }
    __syncwarp();

    for (int sel = 0; sel < KNNK; sel++) {
        float bv = FLT_MAX;
        int   bi = 0x7fffffff;
        for (int j = lane; j < NN; j += 32) {
            float v = dw[j];
            if (v < bv) { bv = v; bi = j; }
        }
        #pragma unroll
        for (int o = 16; o; o >>= 1) {
            float ov = __shfl_xor_sync(0xffffffffu, bv, o);
            int   oi = __shfl_xor_sync(0xffffffffu, bi, o);
            if (ov < bv || (ov == bv && oi < bi)) { bv = ov; bi = oi; }
        }
        if (lane == 0) {
            g_idx[((size_t)b * NN + n) * KNNK + sel] = bi;
            dw[bi] = FLT_MAX;
        }
        __syncwarp();
    }
}

// ---------------------------------------------------------------------------
// block reduce helper
// ---------------------------------------------------------------------------
__device__ __forceinline__ float block_sum_128(float v, float* sred, float* sbc)
{
    #pragma unroll
    for (int o = 16; o; o >>= 1) v += __shfl_xor_sync(0xffffffffu, v, o);
    if ((threadIdx.x & 31) == 0) sred[threadIdx.x >> 5] = v;
    __syncthreads();
    if (threadIdx.x == 0) *sbc = sred[0] + sred[1] + sred[2] + sred[3];
    __syncthreads();
    return *sbc;
}

// ---------------------------------------------------------------------------
// Kernel 2: fused per-point block. One block per (b, n).
// ---------------------------------------------------------------------------
__global__ void __launch_bounds__(128, 4)
fused_kernel(const float* __restrict__ x,
             const float* __restrict__ Wh,
             const float* __restrict__ g1, const float* __restrict__ b1,
             const float* __restrict__ g2, const float* __restrict__ b2,
             const float* __restrict__ lnqw, const float* __restrict__ lnqb,
             const float* __restrict__ lnvw, const float* __restrict__ lnvb,
             const float* __restrict__ lnow, const float* __restrict__ lnob,
             float* __restrict__ out)
{
    const int bn = blockIdx.x;
    const int b  = bn >> 11;
    const int n  = bn & (NN - 1);
    const int t  = threadIdx.x;

    __shared__ __align__(16) float sF [KNNK * CCC];
    __shared__ __align__(16) float sH1[KNNK * CH];
    __shared__ __align__(16) float sH2[KNNK * CH];
    __shared__ __align__(16) float sFQ[CH];
    __shared__ __align__(16) float sQ [NHEAD * DIMK];
    __shared__ __align__(16) float sV [KNNK * DIMV];
    __shared__ __align__(16) float sKK[KNNK * DIMK];
    __shared__ __align__(16) float sKV[DIMK * DIMV];
    __shared__ __align__(16) float sCF[CFE];
    __shared__ int   sIdx[KNNK];
    __shared__ float sred[4];
    __shared__ float sbc[1];

    const float* xb = x + (size_t)b * NN * CIN;
    const float* xc = xb + (size_t)n * CIN;
    const float cx = xc[0], cy = xc[1], cz = xc[2];

    if (t < CFE)  sCF[t]  = xc[3 + t];
    if (t < KNNK) sIdx[t] = g_idx[(size_t)bn * KNNK + t];
    __syncthreads();

    // ---- build F = [grouped - center | center | pos] ------------------------
    for (int i = t; i < KNNK * CFE; i += 128) {
        const int k = i >> 6, c = i & 63;
        const float* np = xb + (size_t)sIdx[k] * CIN;
        const float cf = sCF[c];
        sF[k * CCC + c]       = np[3 + c] - cf;
        sF[k * CCC + CFE + c] = cf;
    }
    for (int i = t; i < KNNK * DIMV; i += 128) {
        const int k = i / DIMV, vd = i % DIMV;
        const float* np = xb + (size_t)sIdx[k] * CIN;
        const float rx = np[0] - cx, ry = np[1] - cy, rz = np[2] - cz;
        sF[k * CCC + 2 * CFE + vd] =
            Wh[vd * 3 + 0] * rx + Wh[vd * 3 + 1] * ry + Wh[vd * 3 + 2] * rz;
    }
    __syncthreads();

    const float bn_rs = rsqrtf(1.0f + EPSF);

    // ---- GEMM1: h1 = relu(bn1(W1 @ F)) --------------------------------------
    {
        const int o  = t & 63;
        const int kg = t >> 6;
        ull acc[10];
        #pragma unroll
        for (int j = 0; j < 10; j++) acc[j] = 0ull;
        for (int c4 = 0; c4 < CCC / 4; c4++) {
            const ulonglong2 w = ldp(&W1p[c4 * 64 + o]);
            #pragma unroll
            for (int j = 0; j < 10; j++) {
                const ulonglong2 f = ldp(&sF[(kg + 2 * j) * CCC + 4 * c4]);
                ffma2(acc[j], w.x, f.x);
                ffma2(acc[j], w.y, f.y);
            }
        }
        const float sc = g1[o] * bn_rs;
        const float bo = b1[o];
        #pragma unroll
        for (int j = 0; j < 10; j++)
            sH1[(kg + 2 * j) * CH + o] = fmaxf(hsum2(acc[j]) * sc + bo, 0.f);
    }
    __syncthreads();

    // ---- GEMM2: h2 = relu(bn2(W2 @ h1)) -------------------------------------
    {
        const int o  = t & 63;
        const int kg = t >> 6;
        ull acc[10];
        #pragma unroll
        for (int j = 0; j < 10; j++) acc[j] = 0ull;
        for (int c4 = 0; c4 < CH / 4; c4++) {
            const ulonglong2 w = ldp(&W2p[c4 * 64 + o]);
            #pragma unroll
            for (int j = 0; j < 10; j++) {
                const ulonglong2 f = ldp(&sH1[(kg + 2 * j) * CH + 4 * c4]);
                ffma2(acc[j], w.x, f.x);
                ffma2(acc[j], w.y, f.y);
            }
        }
        const float sc = g2[o] * bn_rs;
        const float bo = b2[o];
        #pragma unroll
        for (int j = 0; j < 10; j++)
            sH2[(kg + 2 * j) * CH + o] = fmaxf(hsum2(acc[j]) * sc + bo, 0.f);
    }
    __syncthreads();

    // ---- feature_q = max over k ----------------------------------------------
    if (t < CH) {
        float m = sH2[t];
        #pragma unroll
        for (int k = 1; k < KNNK; k++) m = fmaxf(m, sH2[k * CH + t]);
        sFQ[t] = m;
    }
    __syncthreads();

    // ---- q = relu(LN_256(W_q @ fq)) -------------------------------------------
    {
        float qv[2];
        #pragma unroll
        for (int r = 0; r < 2; r++) {
            const int o = t + r * 128;
            ull a = 0ull;
            #pragma unroll
            for (int c4 = 0; c4 < CH / 4; c4++) {
                const ulonglong2 w = ldp(&Wqp[c4 * 256 + o]);
                const ulonglong2 f = ldp(&sFQ[4 * c4]);
                ffma2(a, w.x, f.x);
                ffma2(a, w.y, f.y);
            }
            qv[r] = hsum2(a);
        }
        const float s    = block_sum_128(qv[0] + qv[1], sred, sbc);
        const float mean = s * (1.f / 256.f);
        const float d0 = qv[0] - mean, d1 = qv[1] - mean;
        const float vs   = block_sum_128(d0 * d0 + d1 * d1, sred, sbc);
        const float inv  = rsqrtf(vs * (1.f / 256.f) + EPSF);
        #pragma unroll
        for (int r = 0; r < 2; r++) {
            const int o = t + r * 128;
            sQ[o] = fmaxf((qv[r] - mean) * inv * lnqw[o] + lnqb[o], 0.f);
        }
    }

    // ---- v = W_v @ F (pre-LN). thread = (vd = t&15, k0 = t>>4) -----------------
    {
        const int vd = t & 15;
        const int k0 = t >> 4;        // 0..7 -> k = k0, k0+8, (k0+16 if k0<4)
        ull a0 = 0ull, a1 = 0ull, a2 = 0ull;
        const bool has2 = (k0 < 4);   // warp-uniform (warps 0,1 true / 2,3 false)
        for (int c4 = 0; c4 < CCC / 4; c4++) {
            const ulonglong2 w  = ldp(&Wvp[c4 * 16 + vd]);
            const ulonglong2 f0 = ldp(&sF[k0 * CCC + 4 * c4]);
            const ulonglong2 f1 = ldp(&sF[(k0 + 8) * CCC + 4 * c4]);
            ffma2(a0, w.x, f0.x);  ffma2(a0, w.y, f0.y);
            ffma2(a1, w.x, f1.x);  ffma2(a1, w.y, f1.y);
            if (has2) {
                const ulonglong2 f2 = ldp(&sF[(k0 + 16) * CCC + 4 * c4]);
                ffma2(a2, w.x, f2.x);  ffma2(a2, w.y, f2.y);
            }
        }
        sV[k0 * DIMV + vd]        = hsum2(a0);
        sV[(k0 + 8) * DIMV + vd]  = hsum2(a1);
        if (has2) sV[(k0 + 16) * DIMV + vd] = hsum2(a2);
    }
    __syncthreads();

    // ---- LN_16 over v ----------------------------------------------------------
    if (t < KNNK) {
        float m = 0.f;
        #pragma unroll
        for (int vd = 0; vd < DIMV; vd++) m += sV[t * DIMV + vd];
        m *= (1.f / DIMV);
        float var = 0.f;
        #pragma unroll
        for (int vd = 0; vd < DIMV; vd++) {
            const float d = sV[t * DIMV + vd] - m;
            var += d * d;
        }
        var *= (1.f / DIMV);
        const float inv = rsqrtf(var + EPSF);
        #pragma unroll
        for (int vd = 0; vd < DIMV; vd++)
            sV[t * DIMV + vd] = (sV[t * DIMV + vd] - m) * inv * lnvw[vd] + lnvb[vd];
    }

    // ---- kk_raw = W_k @ F. thread = (d = t&31, kb = t>>5) -----------------------
    {
        const int d  = t & 31;
        const int kb = t >> 5;        // 0..3 -> k = kb + 4p, p=0..4
        ull a[5];
        #pragma unroll
        for (int p = 0; p < 5; p++) a[p] = 0ull;
        for (int c4 = 0; c4 < CCC / 4; c4++) {
            const ulonglong2 w = ldp(&Wkp[c4 * 32 + d]);
            #pragma unroll
            for (int p = 0; p < 5; p++) {
                const ulonglong2 f = ldp(&sF[(kb + 4 * p) * CCC + 4 * c4]);
                ffma2(a[p], w.x, f.x);
                ffma2(a[p], w.y, f.y);
            }
        }
        #pragma unroll
        for (int p = 0; p < 5; p++)
            sKK[(kb + 4 * p) * DIMK + d] = hsum2(a[p]);
    }
    __syncthreads();

    // ---- softmax over k ----------------------------------------------------------
    if (t < DIMK) {
        float mx = -FLT_MAX;
        #pragma unroll
        for (int k = 0; k < KNNK; k++) mx = fmaxf(mx, sKK[k * DIMK + t]);
        float sum = 0.f;
        #pragma unroll
        for (int k = 0; k < KNNK; k++) {
            const float e = expf(sKK[k * DIMK + t] - mx);
            sKK[k * DIMK + t] = e;
            sum += e;
        }
        const float inv = 1.f / sum;
        #pragma unroll
        for (int k = 0; k < KNNK; k++) sKK[k * DIMK + t] *= inv;
    }
    __syncthreads();

    // ---- kv[d][v] = sum_k kk[k][d] * v[k][v] ---------------------------------------
    for (int i = t; i < DIMK * DIMV; i += 128) {
        const int d = i >> 4, vd = i & 15;
        float acc = 0.f;
        #pragma unroll
        for (int k = 0; k < KNNK; k++)
            acc += sKK[k * DIMK + d] * sV[k * DIMV + vd];
        sKV[i] = acc;
    }
    __syncthreads();

    // ---- out = LN_128(q @ kv), write transposed --------------------------------------
    {
        const int h = t >> 4, vd = t & 15;
        float acc = 0.f;
        #pragma unroll
        for (int d = 0; d < DIMK; d++)
            acc += sQ[h * DIMK + d] * sKV[d * DIMV + vd];

        const float s    = block_sum_128(acc, sred, sbc);
        const float mean = s * (1.f / COUT);
        const float dd   = acc - mean;
        const float vs   = block_sum_128(dd * dd, sred, sbc);
        const float inv  = rsqrtf(vs * (1.f / COUT) + EPSF);
        const float ov   = (acc - mean) * inv * lnow[t] + lnob[t];

        out[XYZ_TOT + ((size_t)b * COUT + t) * NN + n] = ov;
    }
    if (t < 3) {
        const float v = (t == 0) ? cx : ((t == 1) ? cy : cz);
        out[(size_t)bn * 3 + t] = v;
    }
}

// ---------------------------------------------------------------------------
// launch
// ---------------------------------------------------------------------------
extern "C" void kernel_launch(void* const* d_in, const int* in_sizes, int n_in,
                              void* d_out, int out_size)
{
    const float* x    = (const float*)d_in[0];
    const float* Wh   = (const float*)d_in[1];
    const float* W1   = (const float*)d_in[2];
    const float* g1   = (const float*)d_in[3];
    const float* b1   = (const float*)d_in[4];
    const float* W2   = (const float*)d_in[5];
    const float* g2   = (const float*)d_in[6];
    const float* b2   = (const float*)d_in[7];
    const float* Wq   = (const float*)d_in[8];
    const float* lnqw = (const float*)d_in[9];
    const float* lnqb = (const float*)d_in[10];
    const float* Wv   = (const float*)d_in[11];
    const float* lnvw = (const float*)d_in[12];
    const float* lnvb = (const float*)d_in[13];
    const float* Wk   = (const float*)d_in[14];
    const float* lnow = (const float*)d_in[15];
    const float* lnob = (const float*)d_in[16];
    float* out = (float*)d_out;

    // pack transposed weights (9152 float4 elements)
    const int pack_total = (CCC/4)*CH + (CH/4)*CH + (CH/4)*NHEAD*DIMK
                         + (CCC/4)*DIMV + (CCC/4)*DIMK;
    pack_weights<<<(pack_total + 127) / 128, 128>>>(W1, W2, Wq, Wv, Wk);

    const int knn_smem = (4 * NN + 8 * NN) * (int)sizeof(float);  // 96 KB
    cudaFuncSetAttribute(knn_kernel,
                         cudaFuncAttributeMaxDynamicSharedMemorySize, knn_smem);
    knn_kernel<<<BB * (NN / 8), 256, knn_smem>>>(x);

    fused_kernel<<<BB * NN, 128>>>(x, Wh,
                                   g1, b1, g2, b2,
                                   lnqw, lnqb, lnvw, lnvb,
                                   lnow, lnob,
                                   out);
}

// round 8
// speedup vs baseline: 2.4058x; 1.2145x over previous
#include <cuda_runtime.h>
#include <float.h>
#include <math.h>

// ---------------------------------------------------------------------------
// Problem constants
// ---------------------------------------------------------------------------
#define BB    8
#define NN    2048
#define KNNK  20
#define CIN   67          // 3 xyz + 64 feat
#define CFE   64
#define CCC   144         // 64 gpn + 64 center + 16 pos
#define CR    80          // reduced per-k channels: 64 grouped + 16 pos
#define CH    64
#define DIMV  16
#define DIMK  32
#define NHEAD 8
#define COUT  128
#define EPSF  1e-5f
#define XYZ_TOT (BB*NN*3)

typedef unsigned long long ull;

// scratch (no allocation allowed -> __device__ globals)
__device__ int    g_idx[BB * NN * KNNK];
__device__ float4 W1gp[(CR/4) * CH];            // [c4 0..19][o]   grouped+pos coeffs
__device__ float4 W1dp[(CFE/4) * CH];           // [c4 0..15][o]   W1[:,64:128]-W1[:,:64]
__device__ float4 W2p [(CH/4)  * CH];           // [c4][o]
__device__ float4 Wqp [(CH/4)  * (NHEAD*DIMK)]; // [c4][o]
__device__ float4 Wvgp[(CR/4) * DIMV];          // [c4 0..19][vd]
__device__ float4 Wvdp[(CFE/4) * DIMV];         // [c4 0..15][vd]
__device__ float4 Wkgp[(CR/4) * DIMK];          // [c4 0..19][d]  (const cancels in softmax)

// ---------------------------------------------------------------------------
// packed dual-fp32 FMA helpers
// ---------------------------------------------------------------------------
__device__ __forceinline__ void ffma2(ull& d, ull a, ull b)
{
    asm("fma.rn.f32x2 %0, %1, %2, %0;" : "+l"(d) : "l"(a), "l"(b));
}
__device__ __forceinline__ float hsum2(ull v)
{
    float lo, hi;
    asm("mov.b64 {%0, %1}, %2;" : "=f"(lo), "=f"(hi) : "l"(v));
    return lo + hi;
}
__device__ __forceinline__ ulonglong2 ldp(const void* p)
{
    return *(const ulonglong2*)p;
}

// ---------------------------------------------------------------------------
// Kernel 0: pack weights (transposed + center-folded layouts)
// ---------------------------------------------------------------------------
__global__ void pack_weights(const float* __restrict__ W1, const float* __restrict__ W2,
                             const float* __restrict__ Wq, const float* __restrict__ Wv,
                             const float* __restrict__ Wk)
{
    int i = blockIdx.x * blockDim.x + threadIdx.x;

    if (i < (CR/4)*CH) {                                   // W1gp: 1280
        int c4 = i >> 6, o = i & 63;
        int col = (c4 < 16) ? 4 * c4 : 128 + 4 * (c4 - 16);
        W1gp[i] = *(const float4*)&W1[o * CCC + col];
        return;
    }
    i -= (CR/4)*CH;
    if (i < (CFE/4)*CH) {                                  // W1dp: 1024
        int c4 = i >> 6, o = i & 63;
        float4 a = *(const float4*)&W1[o * CCC + 64 + 4 * c4];
        float4 b = *(const float4*)&W1[o * CCC + 4 * c4];
        W1dp[i] = make_float4(a.x - b.x, a.y - b.y, a.z - b.z, a.w - b.w);
        return;
    }
    i -= (CFE/4)*CH;
    if (i < (CH/4)*CH) {                                   // W2p: 1024
        int c4 = i >> 6, o = i & 63;
        W2p[i] = *(const float4*)&W2[o * CH + 4 * c4];
        return;
    }
    i -= (CH/4)*CH;
    if (i < (CH/4)*NHEAD*DIMK) {                           // Wqp: 4096
        int c4 = i >> 8, o = i & 255;
        Wqp[i] = *(const float4*)&Wq[o * CH + 4 * c4];
        return;
    }
    i -= (CH/4)*NHEAD*DIMK;
    if (i < (CR/4)*DIMV) {                                 // Wvgp: 320
        int c4 = i >> 4, vd = i & 15;
        int col = (c4 < 16) ? 4 * c4 : 128 + 4 * (c4 - 16);
        Wvgp[i] = *(const float4*)&Wv[vd * CCC + col];
        return;
    }
    i -= (CR/4)*DIMV;
    if (i < (CFE/4)*DIMV) {                                // Wvdp: 256
        int c4 = i >> 4, vd = i & 15;
        float4 a = *(const float4*)&Wv[vd * CCC + 64 + 4 * c4];
        float4 b = *(const float4*)&Wv[vd * CCC + 4 * c4];
        Wvdp[i] = make_float4(a.x - b.x, a.y - b.y, a.z - b.z, a.w - b.w);
        return;
    }
    i -= (CFE/4)*DIMV;
    if (i < (CR/4)*DIMK) {                                 // Wkgp: 640
        int c4 = i >> 5, d = i & 31;
        int col = (c4 < 16) ? 4 * c4 : 128 + 4 * (c4 - 16);
        Wkgp[i] = *(const float4*)&Wk[d * CCC + col];
    }
}

// ---------------------------------------------------------------------------
// Kernel 1: brute-force KNN with cached-local-argmin selection
// ---------------------------------------------------------------------------
__global__ void knn_kernel(const float* __restrict__ x)
{
    extern __shared__ float sm[];
    float* sx   = sm;
    float* sy   = sx + NN;
    float* sz   = sy + NN;
    float* ss   = sz + NN;
    float* dist = ss + NN;      // [8][NN]

    const int b     = blockIdx.x >> 8;
    const int qbase = (blockIdx.x & 255) << 3;
    const int t     = threadIdx.x;
    const int w     = t >> 5;
    const int lane  = t & 31;

    for (int j = t; j < NN; j += 256) {
        const float* p = x + ((size_t)b * NN + j) * CIN;
        float a0 = p[0], a1 = p[1], a2 = p[2];
        sx[j] = a0; sy[j] = a1; sz[j] = a2;
        ss[j] = a0 * a0 + a1 * a1 + a2 * a2;
    }
    __syncthreads();

    const int n = qbase + w;
    const float qx = sx[n], qy = sy[n], qz = sz[n], sq = ss[n];
    float* dw = dist + w * NN;

    for (int j = lane; j < NN; j += 32) {
        float dot = qx * sx[j] + qy * sy[j] + qz * sz[j];
        dw[j] = -2.0f * dot + sq + ss[j];
    }
    __syncwarp();

    // cached per-lane stripe min
    float bv = FLT_MAX;
    int   bi = 0x7fffffff;
    #pragma unroll 8
    for (int j = lane; j < NN; j += 32) {
        float v = dw[j];
        if (v < bv) { bv = v; bi = j; }
    }

    for (int sel = 0; sel < KNNK; sel++) {
        float wv = bv;
        int   wi = bi;
        #pragma unroll
        for (int o = 16; o; o >>= 1) {
            float ov = __shfl_xor_sync(0xffffffffu, wv, o);
            int   oi = __shfl_xor_sync(0xffffffffu, wi, o);
            if (ov < wv || (ov == wv && oi < wi)) { wv = ov; wi = oi; }
        }
        if (lane == 0)
            g_idx[((size_t)b * NN + n) * KNNK + sel] = wi;
        if (bi == wi) {               // owner lane rescans its stripe
            dw[wi] = FLT_MAX;
            bv = FLT_MAX; bi = 0x7fffffff;
            #pragma unroll 8
            for (int j = lane; j < NN; j += 32) {
                float v = dw[j];
                if (v < bv) { bv = v; bi = j; }
            }
        }
    }
}

// ---------------------------------------------------------------------------
// block reduce helper
// ---------------------------------------------------------------------------
__device__ __forceinline__ float block_sum_128(float v, float* sred, float* sbc)
{
    #pragma unroll
    for (int o = 16; o; o >>= 1) v += __shfl_xor_sync(0xffffffffu, v, o);
    if ((threadIdx.x & 31) == 0) sred[threadIdx.x >> 5] = v;
    __syncthreads();
    if (threadIdx.x == 0) *sbc = sred[0] + sred[1] + sred[2] + sred[3];
    __syncthreads();
    return *sbc;
}

// ---------------------------------------------------------------------------
// Kernel 2: fused per-point block. One block per (b, n).
// ---------------------------------------------------------------------------
__global__ void __launch_bounds__(128, 4)
fused_kernel(const float* __restrict__ x,
             const float* __restrict__ Wh,
             const float* __restrict__ g1, const float* __restrict__ b1,
             const float* __restrict__ g2, const float* __restrict__ b2,
             const float* __restrict__ lnqw, const float* __restrict__ lnqb,
             const float* __restrict__ lnvw, const float* __restrict__ lnvb,
             const float* __restrict__ lnow, const float* __restrict__ lnob,
             float* __restrict__ out)
{
    const int bn = blockIdx.x;
    const int b  = bn >> 11;
    const int n  = bn & (NN - 1);
    const int t  = threadIdx.x;

    __shared__ __align__(16) float sF [KNNK * CR];      // 20 x 80: [grouped | pos]
    __shared__ __align__(16) float sH1[KNNK * CH];
    __shared__ __align__(16) float sH2[KNNK * CH];
    __shared__ __align__(16) float sFQ[CH];
    __shared__ __align__(16) float sQ [NHEAD * DIMK];
    __shared__ __align__(16) float sV [KNNK * DIMV];
    __shared__ __align__(16) float sKK[KNNK * DIMK];
    __shared__ __align__(16) float sKV[DIMK * DIMV];
    __shared__ __align__(16) float sCF[CFE];
    __shared__ __align__(16) float sC1[CH];             // per-point const for GEMM1
    __shared__ __align__(16) float sCV[DIMV];           // per-point const for v
    __shared__ int   sIdx[KNNK];
    __shared__ float sred[4];
    __shared__ float sbc[1];

    const float* xb = x + (size_t)b * NN * CIN;
    const float* xc = xb + (size_t)n * CIN;
    const float cx = xc[0], cy = xc[1], cz = xc[2];

    if (t < CFE)  sCF[t]  = xc[3 + t];
    if (t < KNNK) sIdx[t] = g_idx[(size_t)bn * KNNK + t];
    __syncthreads();

    // ---- per-point constant vectors (center-folded) --------------------------
    if (t < CH + DIMV) {
        ull a = 0ull;
        if (t < CH) {
            #pragma unroll
            for (int c4 = 0; c4 < CFE / 4; c4++) {
                const ulonglong2 w = ldp(&W1dp[c4 * CH + t]);
                const ulonglong2 f = ldp(&sCF[4 * c4]);
                ffma2(a, w.x, f.x);
                ffma2(a, w.y, f.y);
            }
            sC1[t] = hsum2(a);
        } else {
            const int vd = t - CH;
            #pragma unroll
            for (int c4 = 0; c4 < CFE / 4; c4++) {
                const ulonglong2 w = ldp(&Wvdp[c4 * DIMV + vd]);
                const ulonglong2 f = ldp(&sCF[4 * c4]);
                ffma2(a, w.x, f.x);
                ffma2(a, w.y, f.y);
            }
            sCV[vd] = hsum2(a);
        }
    }

    // ---- build F = [grouped | pos] -------------------------------------------
    for (int i = t; i < KNNK * CFE; i += 128) {
        const int k = i >> 6, c = i & 63;
        const float* np = xb + (size_t)sIdx[k] * CIN;
        sF[k * CR + c] = np[3 + c];
    }
    for (int i = t; i < KNNK * DIMV; i += 128) {
        const int k = i / DIMV, vd = i % DIMV;
        const float* np = xb + (size_t)sIdx[k] * CIN;
        const float rx = np[0] - cx, ry = np[1] - cy, rz = np[2] - cz;
        sF[k * CR + CFE + vd] =
            Wh[vd * 3 + 0] * rx + Wh[vd * 3 + 1] * ry + Wh[vd * 3 + 2] * rz;
    }
    __syncthreads();

    const float bn_rs = rsqrtf(1.0f + EPSF);

    // ---- GEMM1: h1 = relu(bn1(W1g@Fk + c1)) -----------------------------------
    {
        const int o  = t & 63;
        const int kg = t >> 6;
        ull acc[10];
        #pragma unroll
        for (int j = 0; j < 10; j++) acc[j] = 0ull;
        for (int c4 = 0; c4 < CR / 4; c4++) {
            const ulonglong2 w = ldp(&W1gp[c4 * CH + o]);
            #pragma unroll
            for (int j = 0; j < 10; j++) {
                const ulonglong2 f = ldp(&sF[(kg + 2 * j) * CR + 4 * c4]);
                ffma2(acc[j], w.x, f.x);
                ffma2(acc[j], w.y, f.y);
            }
        }
        const float c1 = sC1[o];
        const float sc = g1[o] * bn_rs;
        const float bo = b1[o];
        #pragma unroll
        for (int j = 0; j < 10; j++)
            sH1[(kg + 2 * j) * CH + o] = fmaxf((hsum2(acc[j]) + c1) * sc + bo, 0.f);
    }
    __syncthreads();

    // ---- GEMM2: h2 = relu(bn2(W2 @ h1)) ----------------------------------------
    {
        const int o  = t & 63;
        const int kg = t >> 6;
        ull acc[10];
        #pragma unroll
        for (int j = 0; j < 10; j++) acc[j] = 0ull;
        for (int c4 = 0; c4 < CH / 4; c4++) {
            const ulonglong2 w = ldp(&W2p[c4 * CH + o]);
            #pragma unroll
            for (int j = 0; j < 10; j++) {
                const ulonglong2 f = ldp(&sH1[(kg + 2 * j) * CH + 4 * c4]);
                ffma2(acc[j], w.x, f.x);
                ffma2(acc[j], w.y, f.y);
            }
        }
        const float sc = g2[o] * bn_rs;
        const float bo = b2[o];
        #pragma unroll
        for (int j = 0; j < 10; j++)
            sH2[(kg + 2 * j) * CH + o] = fmaxf(hsum2(acc[j]) * sc + bo, 0.f);
    }
    __syncthreads();

    // ---- feature_q = max over k --------------------------------------------------
    if (t < CH) {
        float m = sH2[t];
        #pragma unroll
        for (int k = 1; k < KNNK; k++) m = fmaxf(m, sH2[k * CH + t]);
        sFQ[t] = m;
    }
    __syncthreads();

    // ---- q = relu(LN_256(W_q @ fq)) ------------------------------------------------
    {
        float qv[2];
        #pragma unroll
        for (int r = 0; r < 2; r++) {
            const int o = t + r * 128;
            ull a = 0ull;
            #pragma unroll
            for (int c4 = 0; c4 < CH / 4; c4++) {
                const ulonglong2 w = ldp(&Wqp[c4 * 256 + o]);
                const ulonglong2 f = ldp(&sFQ[4 * c4]);
                ffma2(a, w.x, f.x);
                ffma2(a, w.y, f.y);
            }
            qv[r] = hsum2(a);
        }
        const float s    = block_sum_128(qv[0] + qv[1], sred, sbc);
        const float mean = s * (1.f / 256.f);
        const float d0 = qv[0] - mean, d1 = qv[1] - mean;
        const float vs   = block_sum_128(d0 * d0 + d1 * d1, sred, sbc);
        const float inv  = rsqrtf(vs * (1.f / 256.f) + EPSF);
        #pragma unroll
        for (int r = 0; r < 2; r++) {
            const int o = t + r * 128;
            sQ[o] = fmaxf((qv[r] - mean) * inv * lnqw[o] + lnqb[o], 0.f);
        }
    }

    // ---- v = Wvg@Fk + cv (pre-LN). thread = (vd = t&15, k0 = t>>4) -----------------
    {
        const int vd = t & 15;
        const int k0 = t >> 4;
        ull a0 = 0ull, a1 = 0ull, a2 = 0ull;
        const bool has2 = (k0 < 4);
        for (int c4 = 0; c4 < CR / 4; c4++) {
            const ulonglong2 w  = ldp(&Wvgp[c4 * DIMV + vd]);
            const ulonglong2 f0 = ldp(&sF[k0 * CR + 4 * c4]);
            const ulonglong2 f1 = ldp(&sF[(k0 + 8) * CR + 4 * c4]);
            ffma2(a0, w.x, f0.x);  ffma2(a0, w.y, f0.y);
            ffma2(a1, w.x, f1.x);  ffma2(a1, w.y, f1.y);
            if (has2) {
                const ulonglong2 f2 = ldp(&sF[(k0 + 16) * CR + 4 * c4]);
                ffma2(a2, w.x, f2.x);  ffma2(a2, w.y, f2.y);
            }
        }
        const float cv = sCV[vd];
        sV[k0 * DIMV + vd]       = hsum2(a0) + cv;
        sV[(k0 + 8) * DIMV + vd] = hsum2(a1) + cv;
        if (has2) sV[(k0 + 16) * DIMV + vd] = hsum2(a2) + cv;
    }
    __syncthreads();

    // ---- LN_16 over v ----------------------------------------------------------------
    if (t < KNNK) {
        float m = 0.f;
        #pragma unroll
        for (int vd = 0; vd < DIMV; vd++) m += sV[t * DIMV + vd];
        m *= (1.f / DIMV);
        float var = 0.f;
        #pragma unroll
        for (int vd = 0; vd < DIMV; vd++) {
            const float d = sV[t * DIMV + vd] - m;
            var += d * d;
        }
        var *= (1.f / DIMV);
        const float inv = rsqrtf(var + EPSF);
        #pragma unroll
        for (int vd = 0; vd < DIMV; vd++)
            sV[t * DIMV + vd] = (sV[t * DIMV + vd] - m) * inv * lnvw[vd] + lnvb[vd];
    }

    // ---- kk_raw = Wkg@Fk (center const cancels in softmax) ---------------------------
    {
        const int d  = t & 31;
        const int kb = t >> 5;
        ull a[5];
        #pragma unroll
        for (int p = 0; p < 5; p++) a[p] = 0ull;
        for (int c4 = 0; c4 < CR / 4; c4++) {
            const ulonglong2 w = ldp(&Wkgp[c4 * DIMK + d]);
            #pragma unroll
            for (int p = 0; p < 5; p++) {
                const ulonglong2 f = ldp(&sF[(kb + 4 * p) * CR + 4 * c4]);
                ffma2(a[p], w.x, f.x);
                ffma2(a[p], w.y, f.y);
            }
        }
        #pragma unroll
        for (int p = 0; p < 5; p++)
            sKK[(kb + 4 * p) * DIMK + d] = hsum2(a[p]);
    }
    __syncthreads();

    // ---- softmax over k -----------------------------------------------------------------
    if (t < DIMK) {
        float mx = -FLT_MAX;
        #pragma unroll
        for (int k = 0; k < KNNK; k++) mx = fmaxf(mx, sKK[k * DIMK + t]);
        float sum = 0.f;
        #pragma unroll
        for (int k = 0; k < KNNK; k++) {
            const float e = expf(sKK[k * DIMK + t] - mx);
            sKK[k * DIMK + t] = e;
            sum += e;
        }
        const float inv = 1.f / sum;
        #pragma unroll
        for (int k = 0; k < KNNK; k++) sKK[k * DIMK + t] *= inv;
    }
    __syncthreads();

    // ---- kv[d][v] = sum_k kk[k][d] * v[k][v] ----------------------------------------------
    for (int i = t; i < DIMK * DIMV; i += 128) {
        const int d = i >> 4, vd = i & 15;
        float acc = 0.f;
        #pragma unroll
        for (int k = 0; k < KNNK; k++)
            acc += sKK[k * DIMK + d] * sV[k * DIMV + vd];
        sKV[i] = acc;
    }
    __syncthreads();

    // ---- out = LN_128(q @ kv), write transposed ---------------------------------------------
    {
        const int h = t >> 4, vd = t & 15;
        float acc = 0.f;
        #pragma unroll
        for (int d = 0; d < DIMK; d++)
            acc += sQ[h * DIMK + d] * sKV[d * DIMV + vd];

        const float s    = block_sum_128(acc, sred, sbc);
        const float mean = s * (1.f / COUT);
        const float dd   = acc - mean;
        const float vs   = block_sum_128(dd * dd, sred, sbc);
        const float inv  = rsqrtf(vs * (1.f / COUT) + EPSF);
        const float ov   = (acc - mean) * inv * lnow[t] + lnob[t];

        out[XYZ_TOT + ((size_t)b * COUT + t) * NN + n] = ov;
    }
    if (t < 3) {
        const float v = (t == 0) ? cx : ((t == 1) ? cy : cz);
        out[(size_t)bn * 3 + t] = v;
    }
}

// ---------------------------------------------------------------------------
// launch
// ---------------------------------------------------------------------------
extern "C" void kernel_launch(void* const* d_in, const int* in_sizes, int n_in,
                              void* d_out, int out_size)
{
    const float* x    = (const float*)d_in[0];
    const float* Wh   = (const float*)d_in[1];
    const float* W1   = (const float*)d_in[2];
    const float* g1   = (const float*)d_in[3];
    const float* b1   = (const float*)d_in[4];
    const float* W2   = (const float*)d_in[5];
    const float* g2   = (const float*)d_in[6];
    const float* b2   = (const float*)d_in[7];
    const float* Wq   = (const float*)d_in[8];
    const float* lnqw = (const float*)d_in[9];
    const float* lnqb = (const float*)d_in[10];
    const float* Wv   = (const float*)d_in[11];
    const float* lnvw = (const float*)d_in[12];
    const float* lnvb = (const float*)d_in[13];
    const float* Wk   = (const float*)d_in[14];
    const float* lnow = (const float*)d_in[15];
    const float* lnob = (const float*)d_in[16];
    float* out = (float*)d_out;

    const int pack_total = (CR/4)*CH + (CFE/4)*CH + (CH/4)*CH + (CH/4)*NHEAD*DIMK
                         + (CR/4)*DIMV + (CFE/4)*DIMV + (CR/4)*DIMK;   // 8640
    pack_weights<<<(pack_total + 127) / 128, 128>>>(W1, W2, Wq, Wv, Wk);

    const int knn_smem = (4 * NN + 8 * NN) * (int)sizeof(float);  // 96 KB
    cudaFuncSetAttribute(knn_kernel,
                         cudaFuncAttributeMaxDynamicSharedMemorySize, knn_smem);
    knn_kernel<<<BB * (NN / 8), 256, knn_smem>>>(x);

    fused_kernel<<<BB * NN, 128>>>(x, Wh,
                                   g1, b1, g2, b2,
                                   lnqw, lnqb, lnvw, lnvb,
                                   lnow, lnob,
                                   out);
}